// round 14
// baseline (speedup 1.0000x reference)
#include <cuda_runtime.h>
#include <math.h>
#include <stdint.h>

#define BB 2
#define LL 2048
#define CC 1024
#define HH 16
#define DD 64
#define MM (BB * LL)
#define KE 3072
#define MAX_SM 4.6051701859880913680f

__device__ uint16_t g_xh[MM * CC],  g_xl[MM * CC];
__device__ uint16_t g_wqh[3 * CC * CC], g_wql[3 * CC * CC];
__device__ uint16_t g_wph[CC * CC], g_wpl[CC * CC];
__device__ uint16_t g_q2[BB * HH * LL * 128];
__device__ uint16_t g_k2[BB * HH * LL * 128];
__device__ uint16_t g_vt2[(size_t)BB * HH * DD * 2 * LL];
__device__ uint16_t g_ah[MM * CC], g_al[MM * CC];
__device__ unsigned g_bmax_bits;   // zero at load; atomicMax idempotent per replay

__device__ __forceinline__ uint32_t smem_u32(const void* p) {
    uint32_t a;
    asm("{ .reg .u64 t; cvta.to.shared.u64 t, %1; cvt.u32.u64 %0, t; }" : "=r"(a) : "l"(p));
    return a;
}
__device__ __forceinline__ void cp16(uint32_t dst, const void* src) {
    asm volatile("cp.async.cg.shared.global [%0], [%1], 16;" :: "r"(dst), "l"(src));
}
#define CP_COMMIT() asm volatile("cp.async.commit_group;")
#define CP_WAIT0()  asm volatile("cp.async.wait_group 0;" ::: "memory")
#define CP_WAIT1()  asm volatile("cp.async.wait_group 1;" ::: "memory")

__device__ __forceinline__ void ldm4(uint32_t& r0, uint32_t& r1, uint32_t& r2, uint32_t& r3, uint32_t a) {
    asm volatile("ldmatrix.sync.aligned.m8n8.x4.shared.b16 {%0,%1,%2,%3}, [%4];"
                 : "=r"(r0), "=r"(r1), "=r"(r2), "=r"(r3) : "r"(a));
}
__device__ __forceinline__ void mma16816(float* c, uint32_t a0, uint32_t a1, uint32_t a2, uint32_t a3,
                                         uint32_t b0, uint32_t b1) {
    asm volatile("mma.sync.aligned.m16n8k16.row.col.f32.bf16.bf16.f32 "
                 "{%0,%1,%2,%3}, {%4,%5,%6,%7}, {%8,%9}, {%0,%1,%2,%3};"
                 : "+f"(c[0]), "+f"(c[1]), "+f"(c[2]), "+f"(c[3])
                 : "r"(a0), "r"(a1), "r"(a2), "r"(a3), "r"(b0), "r"(b1));
}
__device__ __forceinline__ uint32_t pack_bf(float lo, float hi) {
    uint32_t r;
    asm("cvt.rn.bf16x2.f32 %0, %1, %2;" : "=r"(r) : "f"(hi), "f"(lo));
    return r;
}
__device__ __forceinline__ void split2(float a, float b, uint32_t& hi, uint32_t& lo) {
    hi = pack_bf(a, b);
    float ha = __uint_as_float(hi << 16);
    float hb = __uint_as_float(hi & 0xFFFF0000u);
    lo = pack_bf(a - ha, b - hb);
}

// ---------------- fused elementwise split of x, W_qkv, W_proj ----------------
#define NX4  (MM * CC / 4)
#define NWQ4 (3 * CC * CC / 4)
#define NWP4 (CC * CC / 4)
#define NSPLIT (NX4 + NWQ4 + NWP4)

__global__ __launch_bounds__(256) void split_all(
    const float* __restrict__ x, const float* __restrict__ wq, const float* __restrict__ wp)
{
    int i = blockIdx.x * 256 + threadIdx.x;
    const float* src; uint16_t* hi; uint16_t* lo; int idx;
    if (i < NX4)            { src = x;  hi = g_xh;  lo = g_xl;  idx = i; }
    else if (i < NX4 + NWQ4){ src = wq; hi = g_wqh; lo = g_wql; idx = i - NX4; }
    else if (i < NSPLIT)    { src = wp; hi = g_wph; lo = g_wpl; idx = i - NX4 - NWQ4; }
    else return;
    float4 v = ((const float4*)src)[idx];
    uint32_t h01, l01, h23, l23;
    split2(v.x, v.y, h01, l01);
    split2(v.z, v.w, h23, l23);
    uint2 hv; hv.x = h01; hv.y = h23;
    uint2 lv; lv.x = l01; lv.y = l23;
    ((uint2*)hi)[idx] = hv;
    ((uint2*)lo)[idx] = lv;
}

__global__ __launch_bounds__(256) void bmax_reduce(const float* __restrict__ b, int n4)
{
    float m = 0.f;
    for (int i = blockIdx.x * 256 + threadIdx.x; i < n4; i += gridDim.x * 256) {
        float4 v = ((const float4*)b)[i];
        m = fmaxf(m, fmaxf(fmaxf(fabsf(v.x), fabsf(v.y)), fmaxf(fabsf(v.z), fabsf(v.w))));
    }
#pragma unroll
    for (int off = 16; off > 0; off >>= 1)
        m = fmaxf(m, __shfl_xor_sync(0xffffffffu, m, off));
    if ((threadIdx.x & 31) == 0) atomicMax(&g_bmax_bits, __float_as_uint(m));
}

// ---------------- GEMM: 128x128, BK=64, 2-stage, 3 CTAs/SM ----------------
// MODE 0 (QKV): q/k slices fuse bias+L2norm+split -> g_q2/g_k2;
//               v slices fuse bias+transpose+split -> g_vt2 (via smem).
// MODE 1 (proj): plain bias1 + fp32 C.
#define GP 72
#define GEMM_SMEM (2 * 256 * GP * 2)
#define TP 133

template <int MODE>
__global__ __launch_bounds__(128, 3) void gemm_bf16(
    const uint16_t* __restrict__ Ahi, const uint16_t* __restrict__ Alo,
    const uint16_t* __restrict__ Bhi, const uint16_t* __restrict__ Blo,
    const float* __restrict__ bias1, const float* __restrict__ bias2,
    const float* __restrict__ scale_mul, float* __restrict__ C, int N)
{
    extern __shared__ __align__(16) uint8_t gsm[];
    uint32_t sA = smem_u32(gsm);
    uint32_t sB = sA + 2 * 128 * GP * 2;
    const int tid = threadIdx.x, w = tid >> 5, lane = tid & 31;
    const int m0 = blockIdx.y * 128, n0 = blockIdx.x * 128;
    const int wr = w >> 1, wc = w & 1;
    const int mw = wr * 64, nw = wc * 64;
    const int g = lane >> 3, r = lane & 7;
    const int tq = lane >> 2, tr = lane & 3;

    float acc[4][8][4];
#pragma unroll
    for (int a = 0; a < 4; a++)
#pragma unroll
        for (int b = 0; b < 8; b++)
#pragma unroll
            for (int c = 0; c < 4; c++) acc[a][b][c] = 0.f;

#define GLOAD(s, kt) do { \
    const uint16_t* PA = ((kt) < 2048) ? Ahi : Alo; \
    const uint16_t* PB = ((kt) < 1024 || (kt) >= 2048) ? Bhi : Blo; \
    int ka = ((kt) < 2048) ? ((kt) & 1023) : ((kt) - 2048); \
    int kb = (kt) & 1023; \
    _Pragma("unroll") \
    for (int t = 0; t < 16; t++) { \
        int j = tid + t * 128; int row = j >> 3, cc = (j & 7) * 8; \
        if (row < 128) \
            cp16(sA + (uint32_t)(((s) * 128 + row) * GP + cc) * 2, PA + (size_t)(m0 + row) * 1024 + ka + cc); \
        else \
            cp16(sB + (uint32_t)(((s) * 128 + row - 128) * GP + cc) * 2, PB + (size_t)(n0 + row - 128) * 1024 + kb + cc); \
    } } while (0)

    const int NK = KE / 64;
    GLOAD(0, 0); CP_COMMIT();

    for (int it = 0; it < NK; it++) {
        int s = it & 1;
        CP_WAIT0();
        __syncthreads();
        if (it + 1 < NK) { GLOAD(s ^ 1, (it + 1) * 64); CP_COMMIT(); }
        uint32_t baseA = sA + (uint32_t)(s * 128 * GP) * 2;
        uint32_t baseB = sB + (uint32_t)(s * 128 * GP) * 2;
#pragma unroll
        for (int ks = 0; ks < 4; ks++) {
            uint32_t af[4][4];
#pragma unroll
            for (int mi = 0; mi < 4; mi++)
                ldm4(af[mi][0], af[mi][1], af[mi][2], af[mi][3],
                     baseA + (uint32_t)((mw + mi * 16 + r + (g & 1) * 8) * GP + ks * 16 + (g >> 1) * 8) * 2);
#pragma unroll
            for (int nj = 0; nj < 4; nj++) {
                uint32_t b0, b1, b2, b3;
                ldm4(b0, b1, b2, b3,
                     baseB + (uint32_t)((nw + nj * 16 + (g >> 1) * 8 + r) * GP + ks * 16 + (g & 1) * 8) * 2);
#pragma unroll
                for (int mi = 0; mi < 4; mi++) {
                    mma16816(acc[mi][nj * 2 + 0], af[mi][0], af[mi][1], af[mi][2], af[mi][3], b0, b1);
                    mma16816(acc[mi][nj * 2 + 1], af[mi][0], af[mi][1], af[mi][2], af[mi][3], b2, b3);
                }
            }
        }
    }
#undef GLOAD

    if (MODE == 0 && n0 + nw < 2048) {
        // q (region 0) / k (region 1): bias + L2-norm + bf16-split -> g_q2/g_k2
        int region = (n0 + nw) >> 10;
        int h = ((n0 + nw) >> 6) & 15;
        float smv = (region == 0) ? __expf(fminf(scale_mul[h], MAX_SM)) : 1.f;
        uint16_t* G = (region == 0) ? g_q2 : g_k2;
#pragma unroll
        for (int mi = 0; mi < 4; mi++) {
            float ssq0 = 0.f, ssq1 = 0.f;
#pragma unroll
            for (int nt = 0; nt < 8; nt++) {
                int colg = n0 + nw + nt * 8 + tr * 2;
                float b0 = (region == 0) ? bias1[colg] : 0.f;
                float b1 = (region == 0) ? bias1[colg + 1] : 0.f;
                float v0 = acc[mi][nt][0] + b0, v1 = acc[mi][nt][1] + b1;
                float v2 = acc[mi][nt][2] + b0, v3 = acc[mi][nt][3] + b1;
                ssq0 += v0 * v0 + v1 * v1;
                ssq1 += v2 * v2 + v3 * v3;
            }
            ssq0 += __shfl_xor_sync(0xffffffffu, ssq0, 1);
            ssq0 += __shfl_xor_sync(0xffffffffu, ssq0, 2);
            ssq1 += __shfl_xor_sync(0xffffffffu, ssq1, 1);
            ssq1 += __shfl_xor_sync(0xffffffffu, ssq1, 2);
            float inv0 = smv / fmaxf(sqrtf(ssq0), 1e-12f);
            float inv1 = smv / fmaxf(sqrtf(ssq1), 1e-12f);
            int rA = m0 + mw + mi * 16 + tq;
            int bb = rA >> 11, l = rA & 2047;
            size_t dst0 = ((size_t)((bb * 16 + h) * 2048 + l)) * 128;
            size_t dst1 = dst0 + 8 * 128;
#pragma unroll
            for (int nt = 0; nt < 8; nt++) {
                int colg = n0 + nw + nt * 8 + tr * 2;
                float b0 = (region == 0) ? bias1[colg] : 0.f;
                float b1 = (region == 0) ? bias1[colg + 1] : 0.f;
                int d = nt * 8 + tr * 2;
                uint32_t h0, l0, h1, l1;
                split2((acc[mi][nt][0] + b0) * inv0, (acc[mi][nt][1] + b1) * inv0, h0, l0);
                split2((acc[mi][nt][2] + b0) * inv1, (acc[mi][nt][3] + b1) * inv1, h1, l1);
                *(uint32_t*)(G + dst0 + d)      = h0;
                *(uint32_t*)(G + dst0 + 64 + d) = l0;
                *(uint32_t*)(G + dst1 + d)      = h1;
                *(uint32_t*)(G + dst1 + 64 + d) = l1;
            }
        }
    } else if (MODE == 0) {
        // v region: bias + transpose (via retired pipeline smem) + split -> g_vt2
        float* tsm = (float*)gsm;     // [128 cols][TP pitch] fp32, 68.1 KB
        __syncthreads();
#pragma unroll
        for (int mi = 0; mi < 4; mi++) {
#pragma unroll
            for (int nt = 0; nt < 8; nt++) {
                int colT = nw + nt * 8 + tr * 2;
                int row0 = mw + mi * 16 + tq;
                float b0 = bias2[n0 + colT - 2048];
                float b1 = bias2[n0 + colT - 2047];
                tsm[colT * TP + row0]           = acc[mi][nt][0] + b0;
                tsm[(colT + 1) * TP + row0]     = acc[mi][nt][1] + b1;
                tsm[colT * TP + row0 + 8]       = acc[mi][nt][2] + b0;
                tsm[(colT + 1) * TP + row0 + 8] = acc[mi][nt][3] + b1;
            }
        }
        __syncthreads();
        int t = tid;                                  // tile col = d line
        int hq = ((n0 - 2048) + t) >> 6;              // global head
        int dloc = t & 63;
        int bb = m0 >> 11;
        int tok0 = m0 & 2047;
        size_t dbase = ((size_t)((bb * 16 + hq) * 64 + dloc)) * (2 * LL);
#pragma unroll
        for (int half = 0; half < 2; half++) {
            size_t obase = dbase + (size_t)((tok0 >> 6) + half) * 128;
#pragma unroll
            for (int j4 = 0; j4 < 8; j4++) {
                uint32_t hw[4], lw[4];
#pragma unroll
                for (int e = 0; e < 4; e++) {
                    int l = half * 64 + j4 * 8 + e * 2;
                    split2(tsm[t * TP + l], tsm[t * TP + l + 1], hw[e], lw[e]);
                }
                *(uint4*)(g_vt2 + obase + j4 * 8)      = *(uint4*)hw;
                *(uint4*)(g_vt2 + obase + 64 + j4 * 8) = *(uint4*)lw;
            }
        }
    } else {
#pragma unroll
        for (int mi = 0; mi < 4; mi++) {
#pragma unroll
            for (int nt = 0; nt < 8; nt++) {
                int colg = n0 + nw + nt * 8 + tr * 2;
                float b0 = bias1[colg], b1 = bias1[colg + 1];
                int rA = m0 + mw + mi * 16 + tq;
                float2 v0, v1;
                v0.x = acc[mi][nt][0] + b0; v0.y = acc[mi][nt][1] + b1;
                v1.x = acc[mi][nt][2] + b0; v1.y = acc[mi][nt][3] + b1;
                *(float2*)(C + (size_t)rA * N + colg) = v0;
                *(float2*)(C + (size_t)(rA + 8) * N + colg) = v1;
            }
        }
    }
}

// ---------------- flash (R10 winner): 64-row Q tiles, 256 thr, 2 CTAs/SM ----------------
#define FP2 136
#define FQ_OFF 0u
#define FK_OFF 17408u
#define FV_OFF 52224u
#define FLR_OFF 87040u
#define FLASH_SMEM 87808
#define KVSTG 17408u
#define OEP 68

__global__ __launch_bounds__(256, 2) void flash_mma(
    const float* __restrict__ attn_bias, const float* __restrict__ scale_mul)
{
    extern __shared__ __align__(16) uint8_t fsm[];
    uint32_t sb = smem_u32(fsm);
    const int tid = threadIdx.x, w = tid >> 5, lane = tid & 31;
    const int wr = w >> 1, wc = w & 1;
    const int g = lane >> 3, r = lane & 7;
    const int tq = lane >> 2, tr = lane & 3;
    const int q0 = blockIdx.x * 64;
    const int bh = blockIdx.y, b = bh >> 4, h = bh & 15;

    const uint16_t* Qg = g_q2 + ((size_t)bh * LL + q0) * 128;
    const uint16_t* Kg = g_k2 + ((size_t)bh * LL) * 128;
    const uint16_t* Vg = g_vt2 + (size_t)bh * DD * (2 * LL);

#pragma unroll
    for (int t = 0; t < 4; t++) {
        int j = tid + t * 256; int row = j >> 4, cc = (j & 15) * 8;
        cp16(sb + FQ_OFF + (uint32_t)(row * FP2 + cc) * 2, Qg + (size_t)row * 128 + cc);
    }
    CP_COMMIT();
#define LOADKV(cidx, s) do { \
    _Pragma("unroll") \
    for (int t = 0; t < 4; t++) { \
        int j = tid + t * 256; int row = j >> 4, cc = (j & 15) * 8; \
        cp16(sb + FK_OFF + (s) * KVSTG + (uint32_t)(row * FP2 + cc) * 2, Kg + (size_t)((cidx) * 64 + row) * 128 + cc); \
        cp16(sb + FV_OFF + (s) * KVSTG + (uint32_t)(row * FP2 + cc) * 2, Vg + (size_t)row * (2 * LL) + (size_t)(cidx) * 128 + cc); \
    } } while (0)

    LOADKV(0, 0); CP_COMMIT();

    CP_WAIT1();
    __syncthreads();
    uint32_t qf[2][4][4];
#pragma unroll
    for (int sub = 0; sub < 2; sub++)
#pragma unroll
        for (int ks = 0; ks < 4; ks++)
            ldm4(qf[sub][ks][0], qf[sub][ks][1], qf[sub][ks][2], qf[sub][ks][3],
                 sb + FQ_OFF + (uint32_t)((wr * 16 + r + (g & 1) * 8) * FP2 + sub * 64 + ks * 16 + (g >> 1) * 8) * 2);

    const float M = __expf(fminf(scale_mul[h], MAX_SM)) + __uint_as_float(g_bmax_bits);
    float oacc[8][4];
    float lsum[2] = {0.f, 0.f};
#pragma unroll
    for (int n = 0; n < 8; n++)
#pragma unroll
        for (int e = 0; e < 4; e++) oacc[n][e] = 0.f;

    const int QSEL[3] = {0, 0, 1}, SUBB[3] = {0, 64, 0};

    for (int c = 0; c < 32; c++) {
        int s = c & 1;
        CP_WAIT0();
        __syncthreads();
        if (c < 31) { LOADKV(c + 1, s ^ 1); CP_COMMIT(); }

        int ktg = c * 64;
        float2 bb[4][2];
        {
            int rA = wr * 16 + tq;
#pragma unroll
            for (int nt = 0; nt < 4; nt++) {
                int cl = wc * 32 + nt * 8 + tr * 2;
                bb[nt][0] = *(const float2*)(attn_bias + (size_t)(q0 + rA) * LL + ktg + cl);
                bb[nt][1] = *(const float2*)(attn_bias + (size_t)(q0 + rA + 8) * LL + ktg + cl);
            }
        }

        float sacc[4][4];
#pragma unroll
        for (int n = 0; n < 4; n++)
#pragma unroll
            for (int e = 0; e < 4; e++) sacc[n][e] = 0.f;

        uint32_t bK = sb + FK_OFF + s * KVSTG;
#pragma unroll
        for (int p = 0; p < 3; p++) {
            int qs = QSEL[p], bsub = SUBB[p];
#pragma unroll
            for (int ks = 0; ks < 4; ks++) {
#pragma unroll
                for (int nj = 0; nj < 2; nj++) {
                    uint32_t b0, b1, b2, b3;
                    ldm4(b0, b1, b2, b3,
                         bK + (uint32_t)((wc * 32 + nj * 16 + (g >> 1) * 8 + r) * FP2 + bsub + ks * 16 + (g & 1) * 8) * 2);
                    mma16816(sacc[nj * 2 + 0], qf[qs][ks][0], qf[qs][ks][1], qf[qs][ks][2], qf[qs][ks][3], b0, b1);
                    mma16816(sacc[nj * 2 + 1], qf[qs][ks][0], qf[qs][ks][1], qf[qs][ks][2], qf[qs][ks][3], b2, b3);
                }
            }
        }

        uint32_t pHi[2][4], pLo[2][4];
#pragma unroll
        for (int nt = 0; nt < 4; nt++) {
            float p00 = __expf(sacc[nt][0] + bb[nt][0].x - M);
            float p01 = __expf(sacc[nt][1] + bb[nt][0].y - M);
            float p10 = __expf(sacc[nt][2] + bb[nt][1].x - M);
            float p11 = __expf(sacc[nt][3] + bb[nt][1].y - M);
            lsum[0] += p00 + p01;
            lsum[1] += p10 + p11;
            uint32_t hA, lA, hB, lB;
            split2(p00, p01, hA, lA);
            split2(p10, p11, hB, lB);
            int kk = nt >> 1, e = (nt & 1) * 2;
            pHi[kk][e] = hA; pHi[kk][e + 1] = hB;
            pLo[kk][e] = lA; pLo[kk][e + 1] = lB;
        }

        uint32_t bV = sb + FV_OFF + s * KVSTG;
#pragma unroll
        for (int p = 0; p < 3; p++) {
            int bsub = SUBB[p];
#pragma unroll
            for (int ks = 0; ks < 2; ks++) {
                const uint32_t* A = (p < 2) ? pHi[ks] : pLo[ks];
#pragma unroll
                for (int nj = 0; nj < 4; nj++) {
                    uint32_t b0, b1, b2, b3;
                    ldm4(b0, b1, b2, b3,
                         bV + (uint32_t)((nj * 16 + (g >> 1) * 8 + r) * FP2 + bsub + wc * 32 + ks * 16 + (g & 1) * 8) * 2);
                    mma16816(oacc[nj * 2 + 0], A[0], A[1], A[2], A[3], b0, b1);
                    mma16816(oacc[nj * 2 + 1], A[0], A[1], A[2], A[3], b2, b3);
                }
            }
        }
    }
#undef LOADKV

#pragma unroll
    for (int a = 0; a < 2; a++) {
        lsum[a] += __shfl_xor_sync(0xffffffffu, lsum[a], 1);
        lsum[a] += __shfl_xor_sync(0xffffffffu, lsum[a], 2);
    }
    float* lred = (float*)(fsm + FLR_OFF);
    float* obuf = (float*)(fsm + FQ_OFF);
    __syncthreads();
    if (tr == 0) {
        lred[(wr * 16 + tq) * 2 + wc] = lsum[0];
        lred[(wr * 16 + tq + 8) * 2 + wc] = lsum[1];
    }
    if (wc == 1) {
#pragma unroll
        for (int nj = 0; nj < 8; nj++) {
            int cl = nj * 8 + tr * 2;
            *(float2*)&obuf[(wr * 16 + tq) * OEP + cl]     = make_float2(oacc[nj][0], oacc[nj][1]);
            *(float2*)&obuf[(wr * 16 + tq + 8) * OEP + cl] = make_float2(oacc[nj][2], oacc[nj][3]);
        }
    }
    __syncthreads();
    if (wc == 0) {
        int rA = wr * 16 + tq;
        float inv0 = 1.f / (lred[rA * 2] + lred[rA * 2 + 1]);
        float inv1 = 1.f / (lred[(rA + 8) * 2] + lred[(rA + 8) * 2 + 1]);
        size_t r0g = (size_t)(b * LL + q0 + rA) * CC + h * DD;
        size_t r1g = (size_t)(b * LL + q0 + rA + 8) * CC + h * DD;
#pragma unroll
        for (int nj = 0; nj < 8; nj++) {
            int cl = nj * 8 + tr * 2;
            float2 o0 = *(float2*)&obuf[rA * OEP + cl];
            float2 o1 = *(float2*)&obuf[(rA + 8) * OEP + cl];
            uint32_t hA, lA, hB, lB;
            split2((oacc[nj][0] + o0.x) * inv0, (oacc[nj][1] + o0.y) * inv0, hA, lA);
            split2((oacc[nj][2] + o1.x) * inv1, (oacc[nj][3] + o1.y) * inv1, hB, lB);
            *(uint32_t*)(g_ah + r0g + cl) = hA;
            *(uint32_t*)(g_al + r0g + cl) = lA;
            *(uint32_t*)(g_ah + r1g + cl) = hB;
            *(uint32_t*)(g_al + r1g + cl) = lB;
        }
    }
}

extern "C" void kernel_launch(void* const* d_in, const int* in_sizes, int n_in,
                              void* d_out, int out_size)
{
    const float* x         = (const float*)d_in[0];
    const float* attn_bias = (const float*)d_in[1];
    const float* W_qkv     = (const float*)d_in[2];
    const float* q_bias    = (const float*)d_in[3];
    const float* v_bias    = (const float*)d_in[4];
    const float* scale_mul = (const float*)d_in[5];
    const float* W_proj    = (const float*)d_in[6];
    const float* b_proj    = (const float*)d_in[7];
    float* out = (float*)d_out;

    uint16_t *xh, *xl, *wqh, *wql, *wph, *wpl, *ah, *al;
    cudaGetSymbolAddress((void**)&xh, g_xh);   cudaGetSymbolAddress((void**)&xl, g_xl);
    cudaGetSymbolAddress((void**)&wqh, g_wqh); cudaGetSymbolAddress((void**)&wql, g_wql);
    cudaGetSymbolAddress((void**)&wph, g_wph); cudaGetSymbolAddress((void**)&wpl, g_wpl);
    cudaGetSymbolAddress((void**)&ah, g_ah);   cudaGetSymbolAddress((void**)&al, g_al);

    cudaFuncSetAttribute(gemm_bf16<0>, cudaFuncAttributeMaxDynamicSharedMemorySize, GEMM_SMEM);
    cudaFuncSetAttribute(gemm_bf16<1>, cudaFuncAttributeMaxDynamicSharedMemorySize, GEMM_SMEM);
    cudaFuncSetAttribute(flash_mma, cudaFuncAttributeMaxDynamicSharedMemorySize, FLASH_SMEM);

    split_all<<<(NSPLIT + 255) / 256, 256>>>(x, W_qkv, W_proj);

    gemm_bf16<0><<<dim3(3 * CC / 128, MM / 128), 128, GEMM_SMEM>>>(
        xh, xl, wqh, wql, q_bias, v_bias, scale_mul, nullptr, 3 * CC);

    bmax_reduce<<<512, 256>>>(attn_bias, LL * LL / 4);

    flash_mma<<<dim3(LL / 64, BB * HH), 256, FLASH_SMEM>>>(attn_bias, scale_mul);

    gemm_bf16<1><<<dim3(CC / 128, MM / 128), 128, GEMM_SMEM>>>(
        ah, al, wph, wpl, b_proj, nullptr, nullptr, out, CC);
}

// round 16
// speedup vs baseline: 1.0268x; 1.0268x over previous
#include <cuda_runtime.h>
#include <math.h>
#include <stdint.h>

#define BB 2
#define LL 2048
#define CC 1024
#define HH 16
#define DD 64
#define MM (BB * LL)
#define KE 3072
#define MAX_SM 4.6051701859880913680f

__device__ uint16_t g_xh[MM * CC],  g_xl[MM * CC];
__device__ uint16_t g_wqh[3 * CC * CC], g_wql[3 * CC * CC];
__device__ uint16_t g_wph[CC * CC], g_wpl[CC * CC];
__device__ uint16_t g_q2[BB * HH * LL * 128];
__device__ uint16_t g_k2[BB * HH * LL * 128];
__device__ uint16_t g_vt2[(size_t)BB * HH * DD * 2 * LL];
__device__ uint16_t g_ah[MM * CC], g_al[MM * CC];
__device__ unsigned g_bmax_bits;   // zero at load; atomicMax idempotent per replay

__device__ __forceinline__ uint32_t smem_u32(const void* p) {
    uint32_t a;
    asm("{ .reg .u64 t; cvta.to.shared.u64 t, %1; cvt.u32.u64 %0, t; }" : "=r"(a) : "l"(p));
    return a;
}
__device__ __forceinline__ void cp16(uint32_t dst, const void* src) {
    asm volatile("cp.async.cg.shared.global [%0], [%1], 16;" :: "r"(dst), "l"(src));
}
#define CP_COMMIT() asm volatile("cp.async.commit_group;")
#define CP_WAIT0()  asm volatile("cp.async.wait_group 0;" ::: "memory")
#define CP_WAIT1()  asm volatile("cp.async.wait_group 1;" ::: "memory")

__device__ __forceinline__ void ldm4(uint32_t& r0, uint32_t& r1, uint32_t& r2, uint32_t& r3, uint32_t a) {
    asm volatile("ldmatrix.sync.aligned.m8n8.x4.shared.b16 {%0,%1,%2,%3}, [%4];"
                 : "=r"(r0), "=r"(r1), "=r"(r2), "=r"(r3) : "r"(a));
}
__device__ __forceinline__ void mma16816(float* c, uint32_t a0, uint32_t a1, uint32_t a2, uint32_t a3,
                                         uint32_t b0, uint32_t b1) {
    asm volatile("mma.sync.aligned.m16n8k16.row.col.f32.bf16.bf16.f32 "
                 "{%0,%1,%2,%3}, {%4,%5,%6,%7}, {%8,%9}, {%0,%1,%2,%3};"
                 : "+f"(c[0]), "+f"(c[1]), "+f"(c[2]), "+f"(c[3])
                 : "r"(a0), "r"(a1), "r"(a2), "r"(a3), "r"(b0), "r"(b1));
}
__device__ __forceinline__ uint32_t pack_bf(float lo, float hi) {
    uint32_t r;
    asm("cvt.rn.bf16x2.f32 %0, %1, %2;" : "=r"(r) : "f"(hi), "f"(lo));
    return r;
}
__device__ __forceinline__ void split2(float a, float b, uint32_t& hi, uint32_t& lo) {
    hi = pack_bf(a, b);
    float ha = __uint_as_float(hi << 16);
    float hb = __uint_as_float(hi & 0xFFFF0000u);
    lo = pack_bf(a - ha, b - hb);
}

// ---------------- fused elementwise split of x, W_qkv, W_proj ----------------
#define NX4  (MM * CC / 4)
#define NWQ4 (3 * CC * CC / 4)
#define NWP4 (CC * CC / 4)
#define NSPLIT (NX4 + NWQ4 + NWP4)

__global__ __launch_bounds__(256) void split_all(
    const float* __restrict__ x, const float* __restrict__ wq, const float* __restrict__ wp)
{
    int i = blockIdx.x * 256 + threadIdx.x;
    const float* src; uint16_t* hi; uint16_t* lo; int idx;
    if (i < NX4)            { src = x;  hi = g_xh;  lo = g_xl;  idx = i; }
    else if (i < NX4 + NWQ4){ src = wq; hi = g_wqh; lo = g_wql; idx = i - NX4; }
    else if (i < NSPLIT)    { src = wp; hi = g_wph; lo = g_wpl; idx = i - NX4 - NWQ4; }
    else return;
    float4 v = ((const float4*)src)[idx];
    uint32_t h01, l01, h23, l23;
    split2(v.x, v.y, h01, l01);
    split2(v.z, v.w, h23, l23);
    uint2 hv; hv.x = h01; hv.y = h23;
    uint2 lv; lv.x = l01; lv.y = l23;
    ((uint2*)hi)[idx] = hv;
    ((uint2*)lo)[idx] = lv;
}

__global__ __launch_bounds__(256) void bmax_reduce(const float* __restrict__ b, int n4)
{
    float m = 0.f;
    for (int i = blockIdx.x * 256 + threadIdx.x; i < n4; i += gridDim.x * 256) {
        float4 v = ((const float4*)b)[i];
        m = fmaxf(m, fmaxf(fmaxf(fabsf(v.x), fabsf(v.y)), fmaxf(fabsf(v.z), fabsf(v.w))));
    }
#pragma unroll
    for (int off = 16; off > 0; off >>= 1)
        m = fmaxf(m, __shfl_xor_sync(0xffffffffu, m, off));
    if ((threadIdx.x & 31) == 0) atomicMax(&g_bmax_bits, __float_as_uint(m));
}

// ---------------- GEMM: 128x128, BK=64, 2-stage, 3 CTAs/SM ----------------
#define GP 72
#define GEMM_SMEM (2 * 256 * GP * 2)
#define TP 133

template <int MODE>
__global__ __launch_bounds__(128, 3) void gemm_bf16(
    const uint16_t* __restrict__ Ahi, const uint16_t* __restrict__ Alo,
    const uint16_t* __restrict__ Bhi, const uint16_t* __restrict__ Blo,
    const float* __restrict__ bias1, const float* __restrict__ bias2,
    const float* __restrict__ scale_mul, float* __restrict__ C, int N)
{
    extern __shared__ __align__(16) uint8_t gsm[];
    uint32_t sA = smem_u32(gsm);
    uint32_t sB = sA + 2 * 128 * GP * 2;
    const int tid = threadIdx.x, w = tid >> 5, lane = tid & 31;
    const int m0 = blockIdx.y * 128, n0 = blockIdx.x * 128;
    const int wr = w >> 1, wc = w & 1;
    const int mw = wr * 64, nw = wc * 64;
    const int g = lane >> 3, r = lane & 7;
    const int tq = lane >> 2, tr = lane & 3;

    float acc[4][8][4];
#pragma unroll
    for (int a = 0; a < 4; a++)
#pragma unroll
        for (int b = 0; b < 8; b++)
#pragma unroll
            for (int c = 0; c < 4; c++) acc[a][b][c] = 0.f;

#define GLOAD(s, kt) do { \
    const uint16_t* PA = ((kt) < 2048) ? Ahi : Alo; \
    const uint16_t* PB = ((kt) < 1024 || (kt) >= 2048) ? Bhi : Blo; \
    int ka = ((kt) < 2048) ? ((kt) & 1023) : ((kt) - 2048); \
    int kb = (kt) & 1023; \
    _Pragma("unroll") \
    for (int t = 0; t < 16; t++) { \
        int j = tid + t * 128; int row = j >> 3, cc = (j & 7) * 8; \
        if (row < 128) \
            cp16(sA + (uint32_t)(((s) * 128 + row) * GP + cc) * 2, PA + (size_t)(m0 + row) * 1024 + ka + cc); \
        else \
            cp16(sB + (uint32_t)(((s) * 128 + row - 128) * GP + cc) * 2, PB + (size_t)(n0 + row - 128) * 1024 + kb + cc); \
    } } while (0)

    const int NK = KE / 64;
    GLOAD(0, 0); CP_COMMIT();

    for (int it = 0; it < NK; it++) {
        int s = it & 1;
        CP_WAIT0();
        __syncthreads();
        if (it + 1 < NK) { GLOAD(s ^ 1, (it + 1) * 64); CP_COMMIT(); }
        uint32_t baseA = sA + (uint32_t)(s * 128 * GP) * 2;
        uint32_t baseB = sB + (uint32_t)(s * 128 * GP) * 2;
#pragma unroll
        for (int ks = 0; ks < 4; ks++) {
            uint32_t af[4][4];
#pragma unroll
            for (int mi = 0; mi < 4; mi++)
                ldm4(af[mi][0], af[mi][1], af[mi][2], af[mi][3],
                     baseA + (uint32_t)((mw + mi * 16 + r + (g & 1) * 8) * GP + ks * 16 + (g >> 1) * 8) * 2);
#pragma unroll
            for (int nj = 0; nj < 4; nj++) {
                uint32_t b0, b1, b2, b3;
                ldm4(b0, b1, b2, b3,
                     baseB + (uint32_t)((nw + nj * 16 + (g >> 1) * 8 + r) * GP + ks * 16 + (g & 1) * 8) * 2);
#pragma unroll
                for (int mi = 0; mi < 4; mi++) {
                    mma16816(acc[mi][nj * 2 + 0], af[mi][0], af[mi][1], af[mi][2], af[mi][3], b0, b1);
                    mma16816(acc[mi][nj * 2 + 1], af[mi][0], af[mi][1], af[mi][2], af[mi][3], b2, b3);
                }
            }
        }
    }
#undef GLOAD

    if (MODE == 0 && n0 + nw < 2048) {
        int region = (n0 + nw) >> 10;
        int h = ((n0 + nw) >> 6) & 15;
        float smv = (region == 0) ? __expf(fminf(scale_mul[h], MAX_SM)) : 1.f;
        uint16_t* G = (region == 0) ? g_q2 : g_k2;
#pragma unroll
        for (int mi = 0; mi < 4; mi++) {
            float ssq0 = 0.f, ssq1 = 0.f;
#pragma unroll
            for (int nt = 0; nt < 8; nt++) {
                int colg = n0 + nw + nt * 8 + tr * 2;
                float b0 = (region == 0) ? bias1[colg] : 0.f;
                float b1 = (region == 0) ? bias1[colg + 1] : 0.f;
                float v0 = acc[mi][nt][0] + b0, v1 = acc[mi][nt][1] + b1;
                float v2 = acc[mi][nt][2] + b0, v3 = acc[mi][nt][3] + b1;
                ssq0 += v0 * v0 + v1 * v1;
                ssq1 += v2 * v2 + v3 * v3;
            }
            ssq0 += __shfl_xor_sync(0xffffffffu, ssq0, 1);
            ssq0 += __shfl_xor_sync(0xffffffffu, ssq0, 2);
            ssq1 += __shfl_xor_sync(0xffffffffu, ssq1, 1);
            ssq1 += __shfl_xor_sync(0xffffffffu, ssq1, 2);
            float inv0 = smv / fmaxf(sqrtf(ssq0), 1e-12f);
            float inv1 = smv / fmaxf(sqrtf(ssq1), 1e-12f);
            int rA = m0 + mw + mi * 16 + tq;
            int bb = rA >> 11, l = rA & 2047;
            size_t dst0 = ((size_t)((bb * 16 + h) * 2048 + l)) * 128;
            size_t dst1 = dst0 + 8 * 128;
#pragma unroll
            for (int nt = 0; nt < 8; nt++) {
                int colg = n0 + nw + nt * 8 + tr * 2;
                float b0 = (region == 0) ? bias1[colg] : 0.f;
                float b1 = (region == 0) ? bias1[colg + 1] : 0.f;
                int d = nt * 8 + tr * 2;
                uint32_t h0, l0, h1, l1;
                split2((acc[mi][nt][0] + b0) * inv0, (acc[mi][nt][1] + b1) * inv0, h0, l0);
                split2((acc[mi][nt][2] + b0) * inv1, (acc[mi][nt][3] + b1) * inv1, h1, l1);
                *(uint32_t*)(G + dst0 + d)      = h0;
                *(uint32_t*)(G + dst0 + 64 + d) = l0;
                *(uint32_t*)(G + dst1 + d)      = h1;
                *(uint32_t*)(G + dst1 + 64 + d) = l1;
            }
        }
    } else if (MODE == 0) {
        // v region: bias + transpose + split -> g_vt2
        float* tsm = (float*)gsm;
        __syncthreads();
#pragma unroll
        for (int mi = 0; mi < 4; mi++) {
#pragma unroll
            for (int nt = 0; nt < 8; nt++) {
                int colT = nw + nt * 8 + tr * 2;
                int row0 = mw + mi * 16 + tq;
                float b0 = bias2[n0 + colT - 2048];
                float b1 = bias2[n0 + colT - 2047];
                tsm[colT * TP + row0]           = acc[mi][nt][0] + b0;
                tsm[(colT + 1) * TP + row0]     = acc[mi][nt][1] + b1;
                tsm[colT * TP + row0 + 8]       = acc[mi][nt][2] + b0;
                tsm[(colT + 1) * TP + row0 + 8] = acc[mi][nt][3] + b1;
            }
        }
        __syncthreads();
        int t = tid;
        int hq = ((n0 - 2048) + t) >> 6;
        int dloc = t & 63;
        int bb = m0 >> 11;
        int tok0 = m0 & 2047;
        size_t dbase = ((size_t)((bb * 16 + hq) * 64 + dloc)) * (2 * LL);
#pragma unroll
        for (int half = 0; half < 2; half++) {
            size_t obase = dbase + (size_t)((tok0 >> 6) + half) * 128;
#pragma unroll
            for (int j4 = 0; j4 < 8; j4++) {
                uint32_t hw[4], lw[4];
#pragma unroll
                for (int e = 0; e < 4; e++) {
                    int l = half * 64 + j4 * 8 + e * 2;
                    split2(tsm[t * TP + l], tsm[t * TP + l + 1], hw[e], lw[e]);
                }
                *(uint4*)(g_vt2 + obase + j4 * 8)      = *(uint4*)hw;
                *(uint4*)(g_vt2 + obase + 64 + j4 * 8) = *(uint4*)lw;
            }
        }
    } else {
#pragma unroll
        for (int mi = 0; mi < 4; mi++) {
#pragma unroll
            for (int nt = 0; nt < 8; nt++) {
                int colg = n0 + nw + nt * 8 + tr * 2;
                float b0 = bias1[colg], b1 = bias1[colg + 1];
                int rA = m0 + mw + mi * 16 + tq;
                float2 v0, v1;
                v0.x = acc[mi][nt][0] + b0; v0.y = acc[mi][nt][1] + b1;
                v1.x = acc[mi][nt][2] + b0; v1.y = acc[mi][nt][3] + b1;
                *(float2*)(C + (size_t)rA * N + colg) = v0;
                *(float2*)(C + (size_t)(rA + 8) * N + colg) = v1;
            }
        }
    }
}

// ---------------- flash: shared-operand fused passes (ldm4 48->32 per chunk) ----------------
#define FP2 136
#define FQ_OFF 0u
#define FK_OFF 17408u
#define FV_OFF 52224u
#define FLR_OFF 87040u
#define FLASH_SMEM 87808
#define KVSTG 17408u
#define OEP 68

__global__ __launch_bounds__(256, 2) void flash_mma(
    const float* __restrict__ attn_bias, const float* __restrict__ scale_mul)
{
    extern __shared__ __align__(16) uint8_t fsm[];
    uint32_t sb = smem_u32(fsm);
    const int tid = threadIdx.x, w = tid >> 5, lane = tid & 31;
    const int wr = w >> 1, wc = w & 1;
    const int g = lane >> 3, r = lane & 7;
    const int tq = lane >> 2, tr = lane & 3;
    const int q0 = blockIdx.x * 64;
    const int bh = blockIdx.y, b = bh >> 4, h = bh & 15;

    const uint16_t* Qg = g_q2 + ((size_t)bh * LL + q0) * 128;
    const uint16_t* Kg = g_k2 + ((size_t)bh * LL) * 128;
    const uint16_t* Vg = g_vt2 + (size_t)bh * DD * (2 * LL);

#pragma unroll
    for (int t = 0; t < 4; t++) {
        int j = tid + t * 256; int row = j >> 4, cc = (j & 15) * 8;
        cp16(sb + FQ_OFF + (uint32_t)(row * FP2 + cc) * 2, Qg + (size_t)row * 128 + cc);
    }
    CP_COMMIT();
#define LOADKV(cidx, s) do { \
    _Pragma("unroll") \
    for (int t = 0; t < 4; t++) { \
        int j = tid + t * 256; int row = j >> 4, cc = (j & 15) * 8; \
        cp16(sb + FK_OFF + (s) * KVSTG + (uint32_t)(row * FP2 + cc) * 2, Kg + (size_t)((cidx) * 64 + row) * 128 + cc); \
        cp16(sb + FV_OFF + (s) * KVSTG + (uint32_t)(row * FP2 + cc) * 2, Vg + (size_t)row * (2 * LL) + (size_t)(cidx) * 128 + cc); \
    } } while (0)

    LOADKV(0, 0); CP_COMMIT();

    CP_WAIT1();
    __syncthreads();
    uint32_t qf[2][4][4];
#pragma unroll
    for (int sub = 0; sub < 2; sub++)
#pragma unroll
        for (int ks = 0; ks < 4; ks++)
            ldm4(qf[sub][ks][0], qf[sub][ks][1], qf[sub][ks][2], qf[sub][ks][3],
                 sb + FQ_OFF + (uint32_t)((wr * 16 + r + (g & 1) * 8) * FP2 + sub * 64 + ks * 16 + (g >> 1) * 8) * 2);

    const float M = __expf(fminf(scale_mul[h], MAX_SM)) + __uint_as_float(g_bmax_bits);
    float oacc[8][4];
    float lsum[2] = {0.f, 0.f};
#pragma unroll
    for (int n = 0; n < 8; n++)
#pragma unroll
        for (int e = 0; e < 4; e++) oacc[n][e] = 0.f;

    for (int c = 0; c < 32; c++) {
        int s = c & 1;
        CP_WAIT0();
        __syncthreads();
        if (c < 31) { LOADKV(c + 1, s ^ 1); CP_COMMIT(); }

        int ktg = c * 64;
        float2 bb[4][2];
        {
            int rA = wr * 16 + tq;
#pragma unroll
            for (int nt = 0; nt < 4; nt++) {
                int cl = wc * 32 + nt * 8 + tr * 2;
                bb[nt][0] = *(const float2*)(attn_bias + (size_t)(q0 + rA) * LL + ktg + cl);
                bb[nt][1] = *(const float2*)(attn_bias + (size_t)(q0 + rA + 8) * LL + ktg + cl);
            }
        }

        float sacc[4][4];
#pragma unroll
        for (int n = 0; n < 4; n++)
#pragma unroll
            for (int e = 0; e < 4; e++) sacc[n][e] = 0.f;

        uint32_t bK = sb + FK_OFF + s * KVSTG;
        // Khi fragments: consumed by Qhi AND Qlo (one ldm, three mma-streams)
#pragma unroll
        for (int ks = 0; ks < 4; ks++) {
#pragma unroll
            for (int nj = 0; nj < 2; nj++) {
                uint32_t b0, b1, b2, b3;
                ldm4(b0, b1, b2, b3,
                     bK + (uint32_t)((wc * 32 + nj * 16 + (g >> 1) * 8 + r) * FP2 + ks * 16 + (g & 1) * 8) * 2);
                mma16816(sacc[nj * 2 + 0], qf[0][ks][0], qf[0][ks][1], qf[0][ks][2], qf[0][ks][3], b0, b1);
                mma16816(sacc[nj * 2 + 1], qf[0][ks][0], qf[0][ks][1], qf[0][ks][2], qf[0][ks][3], b2, b3);
                mma16816(sacc[nj * 2 + 0], qf[1][ks][0], qf[1][ks][1], qf[1][ks][2], qf[1][ks][3], b0, b1);
                mma16816(sacc[nj * 2 + 1], qf[1][ks][0], qf[1][ks][1], qf[1][ks][2], qf[1][ks][3], b2, b3);
            }
        }
        // Klo fragments: consumed by Qhi only
#pragma unroll
        for (int ks = 0; ks < 4; ks++) {
#pragma unroll
            for (int nj = 0; nj < 2; nj++) {
                uint32_t b0, b1, b2, b3;
                ldm4(b0, b1, b2, b3,
                     bK + (uint32_t)((wc * 32 + nj * 16 + (g >> 1) * 8 + r) * FP2 + 64 + ks * 16 + (g & 1) * 8) * 2);
                mma16816(sacc[nj * 2 + 0], qf[0][ks][0], qf[0][ks][1], qf[0][ks][2], qf[0][ks][3], b0, b1);
                mma16816(sacc[nj * 2 + 1], qf[0][ks][0], qf[0][ks][1], qf[0][ks][2], qf[0][ks][3], b2, b3);
            }
        }

        uint32_t pHi[2][4], pLo[2][4];
#pragma unroll
        for (int nt = 0; nt < 4; nt++) {
            float p00 = __expf(sacc[nt][0] + bb[nt][0].x - M);
            float p01 = __expf(sacc[nt][1] + bb[nt][0].y - M);
            float p10 = __expf(sacc[nt][2] + bb[nt][1].x - M);
            float p11 = __expf(sacc[nt][3] + bb[nt][1].y - M);
            lsum[0] += p00 + p01;
            lsum[1] += p10 + p11;
            uint32_t hA, lA, hB, lB;
            split2(p00, p01, hA, lA);
            split2(p10, p11, hB, lB);
            int kk = nt >> 1, e = (nt & 1) * 2;
            pHi[kk][e] = hA; pHi[kk][e + 1] = hB;
            pLo[kk][e] = lA; pLo[kk][e + 1] = lB;
        }

        uint32_t bV = sb + FV_OFF + s * KVSTG;
        // Vhi fragments: consumed by Phi AND Plo
#pragma unroll
        for (int ks = 0; ks < 2; ks++) {
#pragma unroll
            for (int nj = 0; nj < 4; nj++) {
                uint32_t b0, b1, b2, b3;
                ldm4(b0, b1, b2, b3,
                     bV + (uint32_t)((nj * 16 + (g >> 1) * 8 + r) * FP2 + wc * 32 + ks * 16 + (g & 1) * 8) * 2);
                mma16816(oacc[nj * 2 + 0], pHi[ks][0], pHi[ks][1], pHi[ks][2], pHi[ks][3], b0, b1);
                mma16816(oacc[nj * 2 + 1], pHi[ks][0], pHi[ks][1], pHi[ks][2], pHi[ks][3], b2, b3);
                mma16816(oacc[nj * 2 + 0], pLo[ks][0], pLo[ks][1], pLo[ks][2], pLo[ks][3], b0, b1);
                mma16816(oacc[nj * 2 + 1], pLo[ks][0], pLo[ks][1], pLo[ks][2], pLo[ks][3], b2, b3);
            }
        }
        // Vlo fragments: consumed by Phi only
#pragma unroll
        for (int ks = 0; ks < 2; ks++) {
#pragma unroll
            for (int nj = 0; nj < 4; nj++) {
                uint32_t b0, b1, b2, b3;
                ldm4(b0, b1, b2, b3,
                     bV + (uint32_t)((nj * 16 + (g >> 1) * 8 + r) * FP2 + 64 + wc * 32 + ks * 16 + (g & 1) * 8) * 2);
                mma16816(oacc[nj * 2 + 0], pHi[ks][0], pHi[ks][1], pHi[ks][2], pHi[ks][3], b0, b1);
                mma16816(oacc[nj * 2 + 1], pHi[ks][0], pHi[ks][1], pHi[ks][2], pHi[ks][3], b2, b3);
            }
        }
    }
#undef LOADKV

#pragma unroll
    for (int a = 0; a < 2; a++) {
        lsum[a] += __shfl_xor_sync(0xffffffffu, lsum[a], 1);
        lsum[a] += __shfl_xor_sync(0xffffffffu, lsum[a], 2);
    }
    float* lred = (float*)(fsm + FLR_OFF);
    float* obuf = (float*)(fsm + FQ_OFF);
    __syncthreads();
    if (tr == 0) {
        lred[(wr * 16 + tq) * 2 + wc] = lsum[0];
        lred[(wr * 16 + tq + 8) * 2 + wc] = lsum[1];
    }
    if (wc == 1) {
#pragma unroll
        for (int nj = 0; nj < 8; nj++) {
            int cl = nj * 8 + tr * 2;
            *(float2*)&obuf[(wr * 16 + tq) * OEP + cl]     = make_float2(oacc[nj][0], oacc[nj][1]);
            *(float2*)&obuf[(wr * 16 + tq + 8) * OEP + cl] = make_float2(oacc[nj][2], oacc[nj][3]);
        }
    }
    __syncthreads();
    if (wc == 0) {
        int rA = wr * 16 + tq;
        float inv0 = 1.f / (lred[rA * 2] + lred[rA * 2 + 1]);
        float inv1 = 1.f / (lred[(rA + 8) * 2] + lred[(rA + 8) * 2 + 1]);
        size_t r0g = (size_t)(b * LL + q0 + rA) * CC + h * DD;
        size_t r1g = (size_t)(b * LL + q0 + rA + 8) * CC + h * DD;
#pragma unroll
        for (int nj = 0; nj < 8; nj++) {
            int cl = nj * 8 + tr * 2;
            float2 o0 = *(float2*)&obuf[rA * OEP + cl];
            float2 o1 = *(float2*)&obuf[(rA + 8) * OEP + cl];
            uint32_t hA, lA, hB, lB;
            split2((oacc[nj][0] + o0.x) * inv0, (oacc[nj][1] + o0.y) * inv0, hA, lA);
            split2((oacc[nj][2] + o1.x) * inv1, (oacc[nj][3] + o1.y) * inv1, hB, lB);
            *(uint32_t*)(g_ah + r0g + cl) = hA;
            *(uint32_t*)(g_al + r0g + cl) = lA;
            *(uint32_t*)(g_ah + r1g + cl) = hB;
            *(uint32_t*)(g_al + r1g + cl) = lB;
        }
    }
}

extern "C" void kernel_launch(void* const* d_in, const int* in_sizes, int n_in,
                              void* d_out, int out_size)
{
    const float* x         = (const float*)d_in[0];
    const float* attn_bias = (const float*)d_in[1];
    const float* W_qkv     = (const float*)d_in[2];
    const float* q_bias    = (const float*)d_in[3];
    const float* v_bias    = (const float*)d_in[4];
    const float* scale_mul = (const float*)d_in[5];
    const float* W_proj    = (const float*)d_in[6];
    const float* b_proj    = (const float*)d_in[7];
    float* out = (float*)d_out;

    uint16_t *xh, *xl, *wqh, *wql, *wph, *wpl, *ah, *al;
    cudaGetSymbolAddress((void**)&xh, g_xh);   cudaGetSymbolAddress((void**)&xl, g_xl);
    cudaGetSymbolAddress((void**)&wqh, g_wqh); cudaGetSymbolAddress((void**)&wql, g_wql);
    cudaGetSymbolAddress((void**)&wph, g_wph); cudaGetSymbolAddress((void**)&wpl, g_wpl);
    cudaGetSymbolAddress((void**)&ah, g_ah);   cudaGetSymbolAddress((void**)&al, g_al);

    cudaFuncSetAttribute(gemm_bf16<0>, cudaFuncAttributeMaxDynamicSharedMemorySize, GEMM_SMEM);
    cudaFuncSetAttribute(gemm_bf16<1>, cudaFuncAttributeMaxDynamicSharedMemorySize, GEMM_SMEM);
    cudaFuncSetAttribute(flash_mma, cudaFuncAttributeMaxDynamicSharedMemorySize, FLASH_SMEM);

    split_all<<<(NSPLIT + 255) / 256, 256>>>(x, W_qkv, W_proj);

    gemm_bf16<0><<<dim3(3 * CC / 128, MM / 128), 128, GEMM_SMEM>>>(
        xh, xl, wqh, wql, q_bias, v_bias, scale_mul, nullptr, 3 * CC);

    bmax_reduce<<<512, 256>>>(attn_bias, LL * LL / 4);

    flash_mma<<<dim3(LL / 64, BB * HH), 256, FLASH_SMEM>>>(attn_bias, scale_mul);

    gemm_bf16<1><<<dim3(CC / 128, MM / 128), 128, GEMM_SMEM>>>(
        ah, al, wph, wpl, b_proj, nullptr, nullptr, out, CC);
}